// round 16
// baseline (speedup 1.0000x reference)
#include <cuda_runtime.h>

#define N_ELEMS 400000
#define N_NODES 200000
#define NQ 8
#define NNPE 8
#define EPB 128                          // elements per block (2 threads/elem)
#define NBLK ((N_ELEMS + EPB - 1) / EPB) // 3125

// static scratch (no cudaMalloc allowed)
__device__ float4 g_us4[N_NODES];       // padded nodal displacements
__device__ float  g_partials[4096];
__device__ unsigned int g_done = 0;     // wraps to 0 each launch -> replay-safe

// ---------------------------------------------------------------------------
// Prep: pack us -> float4 table AND stream the state pass-through (R4-proven).
// ---------------------------------------------------------------------------
__global__ __launch_bounds__(256) void prep_kernel(
    const float* __restrict__ us,
    const float* __restrict__ state_old,
    float* __restrict__ out_state,
    int n_state)
{
    int i = blockIdx.x * 256 + threadIdx.x;
    int stride = gridDim.x * 256;
    for (int n = i; n < N_NODES; n += stride) {
        float u0 = us[3 * n + 0];
        float u1 = us[3 * n + 1];
        float u2 = us[3 * n + 2];
        g_us4[n] = make_float4(u0, u1, u2, 0.0f);
    }
    for (int j = i; j < n_state; j += stride)
        out_state[j] = state_old[j];
}

// ---------------------------------------------------------------------------
// Energy: TWO threads per element (each handles 4 quadrature points).
// Pair lanes gather identical addresses -> L1 dedups, no extra wavefronts.
// Scalar FFMA (R4-proven), LDS.128 shape grads, last-block finalize.
// ---------------------------------------------------------------------------
__global__ __launch_bounds__(256, 4) void energy_kernel(
    const float* __restrict__ params,       // [2] (mu, lambda)
    const float* __restrict__ shape_grads,  // [NQ, NNPE, 3]
    const float* __restrict__ JxWs,         // [N_ELEMS, NQ]
    const int*   __restrict__ conns,        // [N_ELEMS, NNPE] int32
    float* __restrict__ out)                // out[0] = pi
{
    // transposed shape grads: sg_t[q][d][n] -> 8 contiguous n per (q,d)
    __shared__ __align__(16) float sg_t[NQ * 3 * NNPE];   // 192 floats
    __shared__ float red[256];
    __shared__ bool  is_last;

    int tid = threadIdx.x;
    if (tid < NQ * 3 * NNPE) {
        int q = tid / 24, r = tid % 24, d = r / 8, n = r % 8;
        sg_t[tid] = shape_grads[(q * NNPE + n) * 3 + d];
    }
    __syncthreads();

    const float mu  = params[0];
    const float lam = params[1];

    int e    = blockIdx.x * EPB + (tid >> 1);
    int half = tid & 1;                  // which 4 q-points this thread owns
    float acc = 0.0f;

    if (e < N_ELEMS) {
        // connectivity: two 16B loads (pair lanes duplicate -> dedup'd)
        const int4* crow = reinterpret_cast<const int4*>(conns + (size_t)e * NNPE);
        int4 c0 = crow[0];
        int4 c1 = crow[1];
        int idx[NNPE] = {c0.x, c0.y, c0.z, c0.w, c1.x, c1.y, c1.z, c1.w};

        // gather nodal displacements: 8 x LDG.128 (pair lanes same address)
        float u[NNPE][3];
        #pragma unroll
        for (int n = 0; n < NNPE; n++) {
            float4 v = __ldg(&g_us4[idx[n]]);
            u[n][0] = v.x; u[n][1] = v.y; u[n][2] = v.z;
        }

        // this thread's 4 quadrature weights: one float4 (16B aligned)
        float4 jwv = *reinterpret_cast<const float4*>(JxWs + (size_t)e * NQ + half * 4);
        float jw[4] = {jwv.x, jwv.y, jwv.z, jwv.w};

        #pragma unroll
        for (int k = 0; k < 4; k++) {
            int q = half * 4 + k;
            float G00, G01, G02, G10, G11, G12, G20, G21, G22;

            // d = 0: one LDS.128 pair gives g[n] for all 8 nodes
            {
                const float4* gp = reinterpret_cast<const float4*>(&sg_t[(q * 3 + 0) * 8]);
                float4 gA = gp[0], gB = gp[1];
                G00 = gA.x*u[0][0]; G10 = gA.x*u[0][1]; G20 = gA.x*u[0][2];
                G00 = fmaf(gA.y, u[1][0], G00); G10 = fmaf(gA.y, u[1][1], G10); G20 = fmaf(gA.y, u[1][2], G20);
                G00 = fmaf(gA.z, u[2][0], G00); G10 = fmaf(gA.z, u[2][1], G10); G20 = fmaf(gA.z, u[2][2], G20);
                G00 = fmaf(gA.w, u[3][0], G00); G10 = fmaf(gA.w, u[3][1], G10); G20 = fmaf(gA.w, u[3][2], G20);
                G00 = fmaf(gB.x, u[4][0], G00); G10 = fmaf(gB.x, u[4][1], G10); G20 = fmaf(gB.x, u[4][2], G20);
                G00 = fmaf(gB.y, u[5][0], G00); G10 = fmaf(gB.y, u[5][1], G10); G20 = fmaf(gB.y, u[5][2], G20);
                G00 = fmaf(gB.z, u[6][0], G00); G10 = fmaf(gB.z, u[6][1], G10); G20 = fmaf(gB.z, u[6][2], G20);
                G00 = fmaf(gB.w, u[7][0], G00); G10 = fmaf(gB.w, u[7][1], G10); G20 = fmaf(gB.w, u[7][2], G20);
            }
            // d = 1
            {
                const float4* gp = reinterpret_cast<const float4*>(&sg_t[(q * 3 + 1) * 8]);
                float4 gA = gp[0], gB = gp[1];
                G01 = gA.x*u[0][0]; G11 = gA.x*u[0][1]; G21 = gA.x*u[0][2];
                G01 = fmaf(gA.y, u[1][0], G01); G11 = fmaf(gA.y, u[1][1], G11); G21 = fmaf(gA.y, u[1][2], G21);
                G01 = fmaf(gA.z, u[2][0], G01); G11 = fmaf(gA.z, u[2][1], G11); G21 = fmaf(gA.z, u[2][2], G21);
                G01 = fmaf(gA.w, u[3][0], G01); G11 = fmaf(gA.w, u[3][1], G11); G21 = fmaf(gA.w, u[3][2], G21);
                G01 = fmaf(gB.x, u[4][0], G01); G11 = fmaf(gB.x, u[4][1], G11); G21 = fmaf(gB.x, u[4][2], G21);
                G01 = fmaf(gB.y, u[5][0], G01); G11 = fmaf(gB.y, u[5][1], G11); G21 = fmaf(gB.y, u[5][2], G21);
                G01 = fmaf(gB.z, u[6][0], G01); G11 = fmaf(gB.z, u[6][1], G11); G21 = fmaf(gB.z, u[6][2], G21);
                G01 = fmaf(gB.w, u[7][0], G01); G11 = fmaf(gB.w, u[7][1], G11); G21 = fmaf(gB.w, u[7][2], G21);
            }
            // d = 2
            {
                const float4* gp = reinterpret_cast<const float4*>(&sg_t[(q * 3 + 2) * 8]);
                float4 gA = gp[0], gB = gp[1];
                G02 = gA.x*u[0][0]; G12 = gA.x*u[0][1]; G22 = gA.x*u[0][2];
                G02 = fmaf(gA.y, u[1][0], G02); G12 = fmaf(gA.y, u[1][1], G12); G22 = fmaf(gA.y, u[1][2], G22);
                G02 = fmaf(gA.z, u[2][0], G02); G12 = fmaf(gA.z, u[2][1], G12); G22 = fmaf(gA.z, u[2][2], G22);
                G02 = fmaf(gA.w, u[3][0], G02); G12 = fmaf(gA.w, u[3][1], G12); G22 = fmaf(gA.w, u[3][2], G22);
                G02 = fmaf(gB.x, u[4][0], G02); G12 = fmaf(gB.x, u[4][1], G12); G22 = fmaf(gB.x, u[4][2], G22);
                G02 = fmaf(gB.y, u[5][0], G02); G12 = fmaf(gB.y, u[5][1], G12); G22 = fmaf(gB.y, u[5][2], G22);
                G02 = fmaf(gB.z, u[6][0], G02); G12 = fmaf(gB.z, u[6][1], G12); G22 = fmaf(gB.z, u[6][2], G22);
                G02 = fmaf(gB.w, u[7][0], G02); G12 = fmaf(gB.w, u[7][1], G12); G22 = fmaf(gB.w, u[7][2], G22);
            }

            float t = G00 + G11 + G22;
            float s = G00*G00 + G01*G01 + G02*G02
                    + G10*G10 + G11*G11 + G12*G12
                    + G20*G20 + G21*G21 + G22*G22;
            // shared 2x2 minors
            float M0 = G11*G22 - G12*G21;
            float M1 = G10*G22 - G12*G20;
            float M2 = G10*G21 - G11*G20;
            float c2 = (G00*G11 - G01*G10) + (G00*G22 - G02*G20) + M0;
            float c3 = G00*M0 - G01*M1 + G02*M2;

            // J - 1 = t + c2 + c3 exactly (det(I+G) expansion)
            float x = t + c2 + c3;
            // log1p(x), degree-6 Taylor (|x| << 1)
            float p = 1.0f + x * (-0.5f + x * (0.333333333f + x * (-0.25f
                        + x * (0.2f + x * (-0.166666667f)))));
            float L = x * p;

            float fs = 0.5f * mu * (2.0f * t + s - 2.0f * L) + 0.5f * lam * L * L;
            acc = fmaf(jw[k], fs, acc);
        }
    }

    // block tree-reduce (deterministic)
    red[tid] = acc;
    __syncthreads();
    #pragma unroll
    for (int off = 128; off > 0; off >>= 1) {
        if (tid < off) red[tid] += red[tid + off];
        __syncthreads();
    }

    if (tid == 0) {
        g_partials[blockIdx.x] = red[0];
        __threadfence();
        unsigned int prev = atomicInc(&g_done, NBLK - 1);  // wraps to 0 -> replay-safe
        is_last = (prev == NBLK - 1);
    }
    __syncthreads();

    // last finished block sums all partials in fixed index order (deterministic)
    if (is_last) {
        float a = 0.0f;
        for (int i = tid; i < NBLK; i += 256) a += __ldcg(&g_partials[i]);
        red[tid] = a;
        __syncthreads();
        #pragma unroll
        for (int off = 128; off > 0; off >>= 1) {
            if (tid < off) red[tid] += red[tid + off];
            __syncthreads();
        }
        if (tid == 0) out[0] = red[0];
    }
}

extern "C" void kernel_launch(void* const* d_in, const int* in_sizes, int n_in,
                              void* d_out, int out_size)
{
    // 0 params, 1 coords, 2 t, 3 us, 4 shape_vals, 5 shape_grads,
    // 6 JxWs, 7 dt, 8 state_old, 9 conns
    const float* params      = (const float*)d_in[0];
    const float* us          = (const float*)d_in[3];
    const float* shape_grads = (const float*)d_in[5];
    const float* JxWs        = (const float*)d_in[6];
    const float* state_old   = (const float*)d_in[8];
    const int*   conns       = (const int*)d_in[9];
    float* out = (float*)d_out;

    int n_state = 0;
    if (out_size > 1) {
        size_t c = (size_t)out_size - 1;
        size_t avail = (size_t)in_sizes[8];
        n_state = (int)(c < avail ? c : avail);
    }

    prep_kernel<<<1184, 256>>>(us, state_old, out + 1, n_state);
    energy_kernel<<<NBLK, 256>>>(params, shape_grads, JxWs, conns, out);
}

// round 17
// speedup vs baseline: 1.1432x; 1.1432x over previous
#include <cuda_runtime.h>

#define N_ELEMS 400000
#define N_NODES 200000
#define NQ 8
#define NNPE 8
#define CBLK 192                         // copy blocks
#define EBLK ((N_ELEMS + 255) / 256)     // 1563 element blocks
#define TBLK (CBLK + EBLK)               // 1755

// static scratch (no cudaMalloc allowed)
__device__ float4 g_us4[N_NODES];        // padded nodal displacements
__device__ float  g_partials[2048];
__device__ unsigned int g_done = 0;      // wraps to 0 each launch -> replay-safe

// ---------------------------------------------------------------------------
// Prep: pack us -> float4 table only (~6MB traffic, ~1us).
// ---------------------------------------------------------------------------
__global__ __launch_bounds__(256) void prep_kernel(const float* __restrict__ us)
{
    int i = blockIdx.x * 256 + threadIdx.x;
    int stride = gridDim.x * 256;
    for (int n = i; n < N_NODES; n += stride) {
        float u0 = us[3 * n + 0];
        float u1 = us[3 * n + 1];
        float u2 = us[3 * n + 2];
        g_us4[n] = make_float4(u0, u1, u2, 0.0f);
    }
}

// ---------------------------------------------------------------------------
// Fused kernel at the PROVEN 64-reg floor:
//  blocks [0, CBLK): state pass-through with .cs hints (no L2 pollution ->
//                    conns/JxWs/us stay L2-resident across graph replays)
//  blocks [CBLK, TBLK): R4-proven element energy (packed-table gather,
//                       scalar FFMA, LDS.128 shape grads)
//  last-arriving block: deterministic fixed-order finalize.
// ---------------------------------------------------------------------------
__global__ __launch_bounds__(256, 4) void energy_kernel(
    const float* __restrict__ params,       // [2] (mu, lambda)
    const float* __restrict__ shape_grads,  // [NQ, NNPE, 3]
    const float* __restrict__ JxWs,         // [N_ELEMS, NQ]
    const int*   __restrict__ conns,        // [N_ELEMS, NNPE] int32
    const float* __restrict__ state_old,    // [N_ELEMS*NQ]
    float* __restrict__ out,                // out[0]=pi, out[1..]=state
    int n_state)
{
    __shared__ __align__(16) float sg_t[NQ * 3 * NNPE];   // [q][d][n]
    __shared__ float red[256];
    __shared__ bool  is_last;

    int tid = threadIdx.x;
    float acc = 0.0f;

    if (blockIdx.x < CBLK) {
        // ------------- copy blocks: streaming, evict-first both sides -------------
        int i = blockIdx.x * 256 + tid;
        int stride = CBLK * 256;
        for (int j = i; j < n_state; j += stride)
            __stcs(&out[1 + j], __ldcs(&state_old[j]));
    } else {
        // ------------- element blocks: R4-proven energy body -------------
        if (tid < NQ * 3 * NNPE) {
            int q = tid / 24, r = tid % 24, d = r / 8, n = r % 8;
            sg_t[tid] = shape_grads[(q * NNPE + n) * 3 + d];
        }
        __syncthreads();

        const float mu  = params[0];
        const float lam = params[1];

        int e = (blockIdx.x - CBLK) * 256 + tid;
        if (e < N_ELEMS) {
            // connectivity: two 16B loads
            const int4* crow = reinterpret_cast<const int4*>(conns + (size_t)e * NNPE);
            int4 c0 = crow[0];
            int4 c1 = crow[1];
            int idx[NNPE] = {c0.x, c0.y, c0.z, c0.w, c1.x, c1.y, c1.z, c1.w};

            // gather nodal displacements: 8 x LDG.128 (L2-resident table)
            float u[NNPE][3];
            #pragma unroll
            for (int n = 0; n < NNPE; n++) {
                float4 v = __ldg(&g_us4[idx[n]]);
                u[n][0] = v.x; u[n][1] = v.y; u[n][2] = v.z;
            }

            // quadrature weights: 2 x float4
            const float4* jrow = reinterpret_cast<const float4*>(JxWs + (size_t)e * NQ);
            float4 jw0 = jrow[0];
            float4 jw1 = jrow[1];
            float jw[NQ] = {jw0.x, jw0.y, jw0.z, jw0.w, jw1.x, jw1.y, jw1.z, jw1.w};

            #pragma unroll
            for (int q = 0; q < NQ; q++) {
                float G00, G01, G02, G10, G11, G12, G20, G21, G22;

                // d = 0: one LDS.128 pair gives g[n] for all 8 nodes
                {
                    const float4* gp = reinterpret_cast<const float4*>(&sg_t[(q * 3 + 0) * 8]);
                    float4 gA = gp[0], gB = gp[1];
                    G00 = gA.x*u[0][0]; G10 = gA.x*u[0][1]; G20 = gA.x*u[0][2];
                    G00 = fmaf(gA.y, u[1][0], G00); G10 = fmaf(gA.y, u[1][1], G10); G20 = fmaf(gA.y, u[1][2], G20);
                    G00 = fmaf(gA.z, u[2][0], G00); G10 = fmaf(gA.z, u[2][1], G10); G20 = fmaf(gA.z, u[2][2], G20);
                    G00 = fmaf(gA.w, u[3][0], G00); G10 = fmaf(gA.w, u[3][1], G10); G20 = fmaf(gA.w, u[3][2], G20);
                    G00 = fmaf(gB.x, u[4][0], G00); G10 = fmaf(gB.x, u[4][1], G10); G20 = fmaf(gB.x, u[4][2], G20);
                    G00 = fmaf(gB.y, u[5][0], G00); G10 = fmaf(gB.y, u[5][1], G10); G20 = fmaf(gB.y, u[5][2], G20);
                    G00 = fmaf(gB.z, u[6][0], G00); G10 = fmaf(gB.z, u[6][1], G10); G20 = fmaf(gB.z, u[6][2], G20);
                    G00 = fmaf(gB.w, u[7][0], G00); G10 = fmaf(gB.w, u[7][1], G10); G20 = fmaf(gB.w, u[7][2], G20);
                }
                // d = 1
                {
                    const float4* gp = reinterpret_cast<const float4*>(&sg_t[(q * 3 + 1) * 8]);
                    float4 gA = gp[0], gB = gp[1];
                    G01 = gA.x*u[0][0]; G11 = gA.x*u[0][1]; G21 = gA.x*u[0][2];
                    G01 = fmaf(gA.y, u[1][0], G01); G11 = fmaf(gA.y, u[1][1], G11); G21 = fmaf(gA.y, u[1][2], G21);
                    G01 = fmaf(gA.z, u[2][0], G01); G11 = fmaf(gA.z, u[2][1], G11); G21 = fmaf(gA.z, u[2][2], G21);
                    G01 = fmaf(gA.w, u[3][0], G01); G11 = fmaf(gA.w, u[3][1], G11); G21 = fmaf(gA.w, u[3][2], G21);
                    G01 = fmaf(gB.x, u[4][0], G01); G11 = fmaf(gB.x, u[4][1], G11); G21 = fmaf(gB.x, u[4][2], G21);
                    G01 = fmaf(gB.y, u[5][0], G01); G11 = fmaf(gB.y, u[5][1], G11); G21 = fmaf(gB.y, u[5][2], G21);
                    G01 = fmaf(gB.z, u[6][0], G01); G11 = fmaf(gB.z, u[6][1], G11); G21 = fmaf(gB.z, u[6][2], G21);
                    G01 = fmaf(gB.w, u[7][0], G01); G11 = fmaf(gB.w, u[7][1], G11); G21 = fmaf(gB.w, u[7][2], G21);
                }
                // d = 2
                {
                    const float4* gp = reinterpret_cast<const float4*>(&sg_t[(q * 3 + 2) * 8]);
                    float4 gA = gp[0], gB = gp[1];
                    G02 = gA.x*u[0][0]; G12 = gA.x*u[0][1]; G22 = gA.x*u[0][2];
                    G02 = fmaf(gA.y, u[1][0], G02); G12 = fmaf(gA.y, u[1][1], G12); G22 = fmaf(gA.y, u[1][2], G22);
                    G02 = fmaf(gA.z, u[2][0], G02); G12 = fmaf(gA.z, u[2][1], G12); G22 = fmaf(gA.z, u[2][2], G22);
                    G02 = fmaf(gA.w, u[3][0], G02); G12 = fmaf(gA.w, u[3][1], G12); G22 = fmaf(gA.w, u[3][2], G22);
                    G02 = fmaf(gB.x, u[4][0], G02); G12 = fmaf(gB.x, u[4][1], G12); G22 = fmaf(gB.x, u[4][2], G22);
                    G02 = fmaf(gB.y, u[5][0], G02); G12 = fmaf(gB.y, u[5][1], G12); G22 = fmaf(gB.y, u[5][2], G22);
                    G02 = fmaf(gB.z, u[6][0], G02); G12 = fmaf(gB.z, u[6][1], G12); G22 = fmaf(gB.z, u[6][2], G22);
                    G02 = fmaf(gB.w, u[7][0], G02); G12 = fmaf(gB.w, u[7][1], G12); G22 = fmaf(gB.w, u[7][2], G22);
                }

                float t = G00 + G11 + G22;
                float s = G00*G00 + G01*G01 + G02*G02
                        + G10*G10 + G11*G11 + G12*G12
                        + G20*G20 + G21*G21 + G22*G22;
                float M0 = G11*G22 - G12*G21;
                float M1 = G10*G22 - G12*G20;
                float M2 = G10*G21 - G11*G20;
                float c2 = (G00*G11 - G01*G10) + (G00*G22 - G02*G20) + M0;
                float c3 = G00*M0 - G01*M1 + G02*M2;

                // J - 1 = t + c2 + c3 exactly (det(I+G) expansion)
                float x = t + c2 + c3;
                // log1p(x), degree-6 Taylor (|x| << 1)
                float p = 1.0f + x * (-0.5f + x * (0.333333333f + x * (-0.25f
                            + x * (0.2f + x * (-0.166666667f)))));
                float L = x * p;

                float fs = 0.5f * mu * (2.0f * t + s - 2.0f * L) + 0.5f * lam * L * L;
                acc = fmaf(jw[q], fs, acc);
            }
        }
    }

    // block tree-reduce (deterministic; copy blocks contribute zeros)
    red[tid] = acc;
    __syncthreads();
    #pragma unroll
    for (int off = 128; off > 0; off >>= 1) {
        if (tid < off) red[tid] += red[tid + off];
        __syncthreads();
    }

    if (tid == 0) {
        g_partials[blockIdx.x] = red[0];
        __threadfence();
        unsigned int prev = atomicInc(&g_done, TBLK - 1);  // wraps to 0 -> replay-safe
        is_last = (prev == TBLK - 1);
    }
    __syncthreads();

    // last finished block sums all partials in fixed index order (deterministic)
    if (is_last) {
        float a = 0.0f;
        for (int i = tid; i < TBLK; i += 256) a += __ldcg(&g_partials[i]);
        red[tid] = a;
        __syncthreads();
        #pragma unroll
        for (int off = 128; off > 0; off >>= 1) {
            if (tid < off) red[tid] += red[tid + off];
            __syncthreads();
        }
        if (tid == 0) out[0] = red[0];
    }
}

extern "C" void kernel_launch(void* const* d_in, const int* in_sizes, int n_in,
                              void* d_out, int out_size)
{
    // 0 params, 1 coords, 2 t, 3 us, 4 shape_vals, 5 shape_grads,
    // 6 JxWs, 7 dt, 8 state_old, 9 conns
    const float* params      = (const float*)d_in[0];
    const float* us          = (const float*)d_in[3];
    const float* shape_grads = (const float*)d_in[5];
    const float* JxWs        = (const float*)d_in[6];
    const float* state_old   = (const float*)d_in[8];
    const int*   conns       = (const int*)d_in[9];
    float* out = (float*)d_out;

    int n_state = 0;
    if (out_size > 1) {
        size_t c = (size_t)out_size - 1;
        size_t avail = (size_t)in_sizes[8];
        n_state = (int)(c < avail ? c : avail);
    }

    prep_kernel<<<782, 256>>>(us);
    energy_kernel<<<TBLK, 256>>>(params, shape_grads, JxWs, conns,
                                 state_old, out, n_state);
}